// round 2
// baseline (speedup 1.0000x reference)
#include <cuda_runtime.h>
#include <cuda_bf16.h>
#include <math.h>

#define BB 2
#define CC 768
#define TT 2048
#define II 768
#define HH 12
#define DH 64
#define SS 16
#define CTXD 512
#define FFD 3072
#define DEPTH 2
#define KSZ 9

typedef long long ll;

// ---------------- scratch (static device memory; no allocs in kernel_launch) ----
__device__ float g_gt [BB * (ll)TT * CC];   // groupnorm output (token-major) / proj_out buffer
__device__ float g_h  [BB * (ll)TT * II];
__device__ float g_y  [BB * (ll)TT * II];
__device__ float g_q  [BB * (ll)TT * II];
__device__ float g_k  [BB * (ll)TT * II];
__device__ float g_v  [BB * (ll)TT * II];
__device__ float g_ao [BB * (ll)TT * II];
__device__ float g_kc [BB * SS * II];
__device__ float g_vc [BB * SS * II];
__device__ float g_yt [BB * (ll)II * TT];   // channel-major FF input
__device__ float g_f1 [BB * (ll)FFD * TT];
__device__ float g_f2 [BB * (ll)II * TT];
__device__ float g_sim[(ll)BB * HH * TT * TT];  // 402 MB attention scores
__device__ float g_gstats[BB * 32 * 2];

// ---------------- GroupNorm ----------------------------------------------------
__global__ void gn_stats_kernel(const float* __restrict__ x, float* __restrict__ stats) {
    __shared__ float rs[256], rq[256];
    int idx = blockIdx.x;               // b*32 + g ; channels-per-group=24, contiguous
    const float* base = x + (ll)idx * 24 * TT;
    const int n = 24 * TT;
    float s = 0.f, q = 0.f;
    for (int i = threadIdx.x; i < n; i += 256) { float v = base[i]; s += v; q += v * v; }
    rs[threadIdx.x] = s; rq[threadIdx.x] = q; __syncthreads();
    for (int st = 128; st > 0; st >>= 1) {
        if (threadIdx.x < st) { rs[threadIdx.x] += rs[threadIdx.x + st]; rq[threadIdx.x] += rq[threadIdx.x + st]; }
        __syncthreads();
    }
    if (threadIdx.x == 0) {
        float mu = rs[0] / (float)n;
        float var = rq[0] / (float)n - mu * mu;
        stats[idx * 2 + 0] = mu;
        stats[idx * 2 + 1] = rsqrtf(var + 1e-6f);
    }
}

__global__ void gn_apply_kernel(const float* __restrict__ x, const float* __restrict__ stats,
                                const float* __restrict__ gs, const float* __restrict__ gb,
                                float* __restrict__ gt) {
    int bc = blockIdx.x;                // b*CC + c
    int b = bc / CC, c = bc % CC;
    int sidx = b * 32 + c / 24;
    float mu = stats[sidx * 2], rstd = stats[sidx * 2 + 1];
    float a = gs[c] * rstd;
    float bias = gb[c] - mu * a;
    const float* xr = x + (ll)bc * TT;
    float* gr = gt + (ll)b * TT * CC + c;
    for (int t = threadIdx.x; t < TT; t += 256)
        gr[(ll)t * CC] = xr[t] * a + bias;
}

// ---------------- generic GEMM: C = alpha * A@B(^T) (+bias_n)(+res) ------------
__global__ void gemm_kernel(
    const float* __restrict__ A, ll sAb, ll sAh, int lda,
    const float* __restrict__ Bm, ll sBb, ll sBh, int ldb,
    float* __restrict__ Cm, ll sCb, ll sCh, int ldc,
    const float* __restrict__ bias,
    const float* __restrict__ res, ll sRb, ll sRh, int ldr,
    int M, int N, int K, float alpha, int zdiv, int transB)
{
    __shared__ float As[16][128];
    __shared__ float Bs[16][128];
    int z = blockIdx.z, zb = z / zdiv, zh = z % zdiv;
    const float* Ab = A + zb * sAb + zh * sAh;
    const float* Bb = Bm + zb * sBb + zh * sBh;
    float* Cb = Cm + zb * sCb + zh * sCh;
    int m0 = blockIdx.y * 128, n0 = blockIdx.x * 128;
    float acc[8][8];
#pragma unroll
    for (int i = 0; i < 8; i++)
#pragma unroll
        for (int j = 0; j < 8; j++) acc[i][j] = 0.f;
    int tid = threadIdx.x, ty = tid >> 4, tx = tid & 15;
    int ar = tid >> 1, ac = (tid & 1) * 8;

    for (int k0 = 0; k0 < K; k0 += 16) {
        {   // A tile (128 x 16) -> As[k][m]
            int m = m0 + ar;
#pragma unroll
            for (int jj = 0; jj < 8; jj++)
                As[ac + jj][ar] = (m < M) ? Ab[(ll)m * lda + k0 + ac + jj] : 0.f;
        }
        if (transB) {
            int n = n0 + ar;
#pragma unroll
            for (int jj = 0; jj < 8; jj++)
                Bs[ac + jj][ar] = (n < N) ? Bb[(ll)n * ldb + k0 + ac + jj] : 0.f;
        } else {
            int rr = tid >> 4, cc = (tid & 15) * 8;
#pragma unroll
            for (int jj = 0; jj < 8; jj++) {
                int n = n0 + cc + jj;
                Bs[rr][cc + jj] = (n < N) ? Bb[(ll)(k0 + rr) * ldb + n] : 0.f;
            }
        }
        __syncthreads();
#pragma unroll
        for (int q = 0; q < 16; q++) {
            float a[8], bv[8];
#pragma unroll
            for (int i = 0; i < 8; i++) a[i] = As[q][ty * 8 + i];
#pragma unroll
            for (int i = 0; i < 8; i++) bv[i] = Bs[q][tx * 8 + i];
#pragma unroll
            for (int i = 0; i < 8; i++)
#pragma unroll
                for (int j = 0; j < 8; j++) acc[i][j] += a[i] * bv[j];
        }
        __syncthreads();
    }

#pragma unroll
    for (int i = 0; i < 8; i++) {
        int m = m0 + ty * 8 + i;
        if (m >= M) continue;
        const float* rr2 = res ? (res + zb * sRb + zh * sRh + (ll)m * ldr) : (const float*)0;
        float* cr = Cb + (ll)m * ldc;
#pragma unroll
        for (int j = 0; j < 8; j++) {
            int n = n0 + tx * 8 + j;
            if (n >= N) continue;
            float vv = acc[i][j] * alpha;
            if (bias) vv += bias[n];
            if (rr2) vv += rr2[n];
            cr[n] = vv;
        }
    }
}

// ---------------- direct conv1d as GEMM (K-dim = Cin*9, time-shifted B loads) --
__global__ void conv_gemm_kernel(const float* __restrict__ W, const float* __restrict__ X,
                                 float* __restrict__ Y, const float* __restrict__ bias,
                                 int M, int Cin, int act)
{
    __shared__ float As[16][128];
    __shared__ float Bs[16][128];
    int b = blockIdx.z;
    const float* Xb = X + (ll)b * Cin * TT;
    float* Yb = Y + (ll)b * M * TT;
    int m0 = blockIdx.y * 128, n0 = blockIdx.x * 128;
    int J = Cin * KSZ;
    float acc[8][8];
#pragma unroll
    for (int i = 0; i < 8; i++)
#pragma unroll
        for (int j = 0; j < 8; j++) acc[i][j] = 0.f;
    int tid = threadIdx.x, ty = tid >> 4, tx = tid & 15;
    int ar = tid >> 1, ac = (tid & 1) * 8;

    for (int j0 = 0; j0 < J; j0 += 16) {
        {
            int m = m0 + ar;
#pragma unroll
            for (int jj = 0; jj < 8; jj++)
                As[ac + jj][ar] = (m < M) ? W[(ll)m * J + j0 + ac + jj] : 0.f;
        }
        {
            int rr = tid >> 4, cc = (tid & 15) * 8;
            int jr = j0 + rr;
            int ch = jr / KSZ, kk = jr % KSZ;
            const float* xrow = Xb + (ll)ch * TT;
#pragma unroll
            for (int jj = 0; jj < 8; jj++) {
                int tp = n0 + cc + jj + kk - 4;
                Bs[rr][cc + jj] = (tp >= 0 && tp < TT) ? xrow[tp] : 0.f;
            }
        }
        __syncthreads();
#pragma unroll
        for (int q = 0; q < 16; q++) {
            float a[8], bv[8];
#pragma unroll
            for (int i = 0; i < 8; i++) a[i] = As[q][ty * 8 + i];
#pragma unroll
            for (int i = 0; i < 8; i++) bv[i] = Bs[q][tx * 8 + i];
#pragma unroll
            for (int i = 0; i < 8; i++)
#pragma unroll
                for (int j = 0; j < 8; j++) acc[i][j] += a[i] * bv[j];
        }
        __syncthreads();
    }

#pragma unroll
    for (int i = 0; i < 8; i++) {
        int m = m0 + ty * 8 + i;
        if (m >= M) continue;
        float bv = bias[m];
        float* yr = Yb + (ll)m * TT;
#pragma unroll
        for (int j = 0; j < 8; j++) {
            int n = n0 + tx * 8 + j;
            float vv = acc[i][j] + bv;
            if (act) vv = vv * normcdff(vv);   // exact GELU
            yr[n] = vv;
        }
    }
}

// ---------------- LayerNorm (per token, optional transposed write) -------------
__global__ void ln_kernel(const float* __restrict__ x, const float* __restrict__ sc,
                          const float* __restrict__ bi, float* __restrict__ y, int transposed)
{
    __shared__ float red[256];
    int token = blockIdx.x;
    const float* xr = x + (ll)token * II;
    int tid = threadIdx.x;
    float v0 = xr[tid], v1 = xr[tid + 256], v2 = xr[tid + 512];
    red[tid] = v0 + v1 + v2; __syncthreads();
    for (int st = 128; st > 0; st >>= 1) {
        if (tid < st) red[tid] += red[tid + st];
        __syncthreads();
    }
    float mu = red[0] * (1.f / (float)II);
    __syncthreads();
    float d0 = v0 - mu, d1 = v1 - mu, d2 = v2 - mu;
    red[tid] = d0 * d0 + d1 * d1 + d2 * d2; __syncthreads();
    for (int st = 128; st > 0; st >>= 1) {
        if (tid < st) red[tid] += red[tid + st];
        __syncthreads();
    }
    float rstd = rsqrtf(red[0] * (1.f / (float)II) + 1e-5f);
    float o0 = d0 * rstd * sc[tid] + bi[tid];
    float o1 = d1 * rstd * sc[tid + 256] + bi[tid + 256];
    float o2 = d2 * rstd * sc[tid + 512] + bi[tid + 512];
    if (!transposed) {
        float* yr = y + (ll)token * II;
        yr[tid] = o0; yr[tid + 256] = o1; yr[tid + 512] = o2;
    } else {
        int b = token >> 11, t = token & (TT - 1);
        float* yb = y + (ll)b * II * TT + t;
        yb[(ll)tid * TT] = o0;
        yb[(ll)(tid + 256) * TT] = o1;
        yb[(ll)(tid + 512) * TT] = o2;
    }
}

// ---------------- row softmax over T=2048 --------------------------------------
__global__ void softmax_kernel(float* __restrict__ sim) {
    __shared__ float buf[TT];
    __shared__ float red[256];
    ll row = blockIdx.x;
    float* p = sim + row * TT;
    int tid = threadIdx.x;
    float m = -1e30f;
    for (int i = tid; i < TT; i += 256) { float v = p[i]; buf[i] = v; m = fmaxf(m, v); }
    red[tid] = m; __syncthreads();
    for (int s = 128; s > 0; s >>= 1) {
        if (tid < s) red[tid] = fmaxf(red[tid], red[tid + s]);
        __syncthreads();
    }
    m = red[0]; __syncthreads();
    float sum = 0.f;
    for (int i = tid; i < TT; i += 256) { float e = expf(buf[i] - m); buf[i] = e; sum += e; }
    red[tid] = sum; __syncthreads();
    for (int s = 128; s > 0; s >>= 1) {
        if (tid < s) red[tid] += red[tid + s];
        __syncthreads();
    }
    float inv = 1.f / red[0];
    for (int i = tid; i < TT; i += 256) p[i] = buf[i] * inv;
}

// ---------------- cross-attention (16 keys): warp per (token, head) ------------
__global__ void cross_attn_kernel(const float* __restrict__ q, const float* __restrict__ kc,
                                  const float* __restrict__ vc, float* __restrict__ out)
{
    __shared__ float sq[HH][DH];
    int token = blockIdx.x;
    int b = token / TT;
    int wid = threadIdx.x >> 5, lane = threadIdx.x & 31;
    const float* qrow = q + (ll)token * II + wid * DH;
    sq[wid][lane] = qrow[lane];
    sq[wid][lane + 32] = qrow[lane + 32];
    __syncwarp();
    const float* kb = kc + (ll)b * SS * II + wid * DH;
    const float* vb = vc + (ll)b * SS * II + wid * DH;
    float s = -1e30f;
    if (lane < SS) {
        s = 0.f;
        const float* kr = kb + lane * II;
#pragma unroll
        for (int d = 0; d < DH; d++) s += sq[wid][d] * kr[d];
        s *= 0.125f;
    }
    float m = s;
    for (int o = 8; o >= 1; o >>= 1) m = fmaxf(m, __shfl_xor_sync(0xffffffffu, m, o));
    float e = (lane < SS) ? expf(s - m) : 0.f;
    float sum = e;
    for (int o = 8; o >= 1; o >>= 1) sum += __shfl_xor_sync(0xffffffffu, sum, o);
    float p = e / sum;   // lanes >= 16: unused (possibly NaN)
    float o0 = 0.f, o1 = 0.f;
#pragma unroll
    for (int j = 0; j < SS; j++) {
        float pj = __shfl_sync(0xffffffffu, p, j);
        const float* vr = vb + j * II;
        o0 += pj * vr[lane];
        o1 += pj * vr[lane + 32];
    }
    float* orow = out + (ll)token * II + wid * DH;
    orow[lane] = o0;
    orow[lane + 32] = o1;
}

// ---------------- misc elementwise ---------------------------------------------
__global__ void add_t_kernel(float* __restrict__ h, const float* __restrict__ f) {
    int token = blockIdx.x;
    int b = token >> 11, t = token & (TT - 1);
    float* hr = h + (ll)token * II;
    const float* fb = f + (ll)b * II * TT + t;
    int tid = threadIdx.x;
    hr[tid]       += fb[(ll)tid * TT];
    hr[tid + 256] += fb[(ll)(tid + 256) * TT];
    hr[tid + 512] += fb[(ll)(tid + 512) * TT];
}

__global__ void final_kernel(const float* __restrict__ proj, const float* __restrict__ x,
                             float* __restrict__ out) {
    int bc = blockIdx.x;
    int b = bc / CC, c = bc % CC;
    const float* pr = proj + (ll)b * TT * CC + c;
    const float* xr = x + (ll)bc * TT;
    float* orow = out + (ll)bc * TT;
    for (int t = threadIdx.x; t < TT; t += 256)
        orow[t] = pr[(ll)t * CC] + xr[t];
}

// ---------------- host orchestration -------------------------------------------
static void gemm(const float* A, ll sAb, ll sAh, int lda,
                 const float* Bm, ll sBb, ll sBh, int ldb, int transB,
                 float* Cm, ll sCb, ll sCh, int ldc,
                 const float* bias, const float* res, ll sRb, ll sRh, int ldr,
                 int M, int N, int K, float alpha, int Z, int zdiv)
{
    dim3 grid((N + 127) / 128, (M + 127) / 128, Z);
    gemm_kernel<<<grid, 256>>>(A, sAb, sAh, lda, Bm, sBb, sBh, ldb,
                               Cm, sCb, sCh, ldc, bias, res, sRb, sRh, ldr,
                               M, N, K, alpha, zdiv, transB);
}

extern "C" void kernel_launch(void* const* d_in, const int* in_sizes, int n_in,
                              void* d_out, int out_size)
{
    (void)in_sizes; (void)n_in; (void)out_size;
    const float* x      = (const float*)d_in[0];
    const float* ctx    = (const float*)d_in[1];
    const float* gn_s   = (const float*)d_in[2];
    const float* gn_b   = (const float*)d_in[3];
    const float* pin_w  = (const float*)d_in[4];
    const float* pin_b  = (const float*)d_in[5];
    const float* n1_s   = (const float*)d_in[6];
    const float* n1_b   = (const float*)d_in[7];
    const float* a1_wq  = (const float*)d_in[8];
    const float* a1_wk  = (const float*)d_in[9];
    const float* a1_wv  = (const float*)d_in[10];
    const float* a1_wo  = (const float*)d_in[11];
    const float* a1_bo  = (const float*)d_in[12];
    const float* n2_s   = (const float*)d_in[13];
    const float* n2_b   = (const float*)d_in[14];
    const float* a2_wq  = (const float*)d_in[15];
    const float* a2_wk  = (const float*)d_in[16];
    const float* a2_wv  = (const float*)d_in[17];
    const float* a2_wo  = (const float*)d_in[18];
    const float* a2_bo  = (const float*)d_in[19];
    const float* n3_s   = (const float*)d_in[20];
    const float* n3_b   = (const float*)d_in[21];
    const float* ff1_w  = (const float*)d_in[22];
    const float* ff1_b  = (const float*)d_in[23];
    const float* ff2_w  = (const float*)d_in[24];
    const float* ff2_b  = (const float*)d_in[25];
    const float* pout_w = (const float*)d_in[26];
    const float* pout_b = (const float*)d_in[27];

    float *gt, *h, *y, *q, *k, *v, *ao, *kc, *vc, *yt, *f1, *f2, *sim, *stats;
    cudaGetSymbolAddress((void**)&gt, g_gt);
    cudaGetSymbolAddress((void**)&h, g_h);
    cudaGetSymbolAddress((void**)&y, g_y);
    cudaGetSymbolAddress((void**)&q, g_q);
    cudaGetSymbolAddress((void**)&k, g_k);
    cudaGetSymbolAddress((void**)&v, g_v);
    cudaGetSymbolAddress((void**)&ao, g_ao);
    cudaGetSymbolAddress((void**)&kc, g_kc);
    cudaGetSymbolAddress((void**)&vc, g_vc);
    cudaGetSymbolAddress((void**)&yt, g_yt);
    cudaGetSymbolAddress((void**)&f1, g_f1);
    cudaGetSymbolAddress((void**)&f2, g_f2);
    cudaGetSymbolAddress((void**)&sim, g_sim);
    cudaGetSymbolAddress((void**)&stats, g_gstats);

    const ll TI = (ll)TT * II;
    const ll TC = (ll)TT * CC;

    // GroupNorm -> gt (token-major)
    gn_stats_kernel<<<BB * 32, 256>>>(x, stats);
    gn_apply_kernel<<<BB * CC, 256>>>(x, stats, gn_s, gn_b, gt);

    // proj_in: h[b,t,i] = gt @ pin_w^T + pin_b
    gemm(gt, TC, 0, CC, pin_w, 0, 0, CC, 1, h, TI, 0, II,
         pin_b, 0, 0, 0, 0, TT, II, CC, 1.f, BB, 1);

    for (int d = 0; d < DEPTH; d++) {
        // ---- self attention ----
        ln_kernel<<<BB * TT, 256>>>(h, n1_s + d * II, n1_b + d * II, y, 0);
        gemm(y, TI, 0, II, a1_wq + (ll)d * II * II, 0, 0, II, 0, q, TI, 0, II,
             0, 0, 0, 0, 0, TT, II, II, 1.f, BB, 1);
        gemm(y, TI, 0, II, a1_wk + (ll)d * II * II, 0, 0, II, 0, k, TI, 0, II,
             0, 0, 0, 0, 0, TT, II, II, 1.f, BB, 1);
        gemm(y, TI, 0, II, a1_wv + (ll)d * II * II, 0, 0, II, 0, v, TI, 0, II,
             0, 0, 0, 0, 0, TT, II, II, 1.f, BB, 1);
        // sim = 0.125 * Q K^T per (b,h)
        gemm(q, TI, DH, II, k, TI, DH, II, 1, sim, (ll)HH * TT * TT, (ll)TT * TT, TT,
             0, 0, 0, 0, 0, TT, TT, DH, 0.125f, BB * HH, HH);
        softmax_kernel<<<BB * HH * TT, 256>>>(sim);
        // ao = P V per (b,h)
        gemm(sim, (ll)HH * TT * TT, (ll)TT * TT, TT, v, TI, DH, II, 0, ao, TI, DH, II,
             0, 0, 0, 0, 0, TT, DH, TT, 1.f, BB * HH, HH);
        // h = ao @ wo + bo + h
        gemm(ao, TI, 0, II, a1_wo + (ll)d * II * II, 0, 0, II, 0, h, TI, 0, II,
             a1_bo + d * II, h, TI, 0, II, TT, II, II, 1.f, BB, 1);

        // ---- cross attention ----
        ln_kernel<<<BB * TT, 256>>>(h, n2_s + d * II, n2_b + d * II, y, 0);
        gemm(y, TI, 0, II, a2_wq + (ll)d * II * II, 0, 0, II, 0, q, TI, 0, II,
             0, 0, 0, 0, 0, TT, II, II, 1.f, BB, 1);
        gemm(ctx, (ll)SS * CTXD, 0, CTXD, a2_wk + (ll)d * CTXD * II, 0, 0, II, 0,
             kc, (ll)SS * II, 0, II, 0, 0, 0, 0, 0, SS, II, CTXD, 1.f, BB, 1);
        gemm(ctx, (ll)SS * CTXD, 0, CTXD, a2_wv + (ll)d * CTXD * II, 0, 0, II, 0,
             vc, (ll)SS * II, 0, II, 0, 0, 0, 0, 0, SS, II, CTXD, 1.f, BB, 1);
        cross_attn_kernel<<<BB * TT, HH * 32>>>(q, kc, vc, ao);
        gemm(ao, TI, 0, II, a2_wo + (ll)d * II * II, 0, 0, II, 0, h, TI, 0, II,
             a2_bo + d * II, h, TI, 0, II, TT, II, II, 1.f, BB, 1);

        // ---- conv feed-forward ----
        ln_kernel<<<BB * TT, 256>>>(h, n3_s + d * II, n3_b + d * II, yt, 1);
        {
            dim3 g1(TT / 128, FFD / 128, BB);
            conv_gemm_kernel<<<g1, 256>>>(ff1_w + (ll)d * FFD * II * KSZ, yt, f1,
                                          ff1_b + d * FFD, FFD, II, 1);
            dim3 g2(TT / 128, II / 128, BB);
            conv_gemm_kernel<<<g2, 256>>>(ff2_w + (ll)d * II * FFD * KSZ, f1, f2,
                                          ff2_b + d * II, II, FFD, 0);
        }
        add_t_kernel<<<BB * TT, 256>>>(h, f2);
    }

    // proj_out + residual with original input
    gemm(h, TI, 0, II, pout_w, 0, 0, II, 1, gt, TC, 0, CC,
         pout_b, 0, 0, 0, 0, TT, CC, II, 1.f, BB, 1);
    final_kernel<<<BB * CC, 256>>>(gt, x, (float*)d_out);
}

// round 3
// speedup vs baseline: 2.2790x; 2.2790x over previous
#include <cuda_runtime.h>
#include <cuda_bf16.h>
#include <math.h>

#define BB 2
#define CC 768
#define TT 2048
#define II 768
#define HH 12
#define DH 64
#define SS 16
#define CTXD 512
#define FFD 3072
#define DEPTH 2
#define KSZ 9

typedef long long ll;

#define KT 32
#define SPAD 4
#define SLD (128 + SPAD)

// ---------------- scratch (static device memory) -------------------------------
__device__ float g_gt [BB * (ll)TT * CC];
__device__ float g_h  [BB * (ll)TT * II];
__device__ float g_y  [BB * (ll)TT * II];
__device__ float g_q  [BB * (ll)TT * II];
__device__ float g_k  [BB * (ll)TT * II];
__device__ float g_v  [BB * (ll)TT * II];
__device__ float g_ao [BB * (ll)TT * II];
__device__ float g_kc [BB * SS * II];
__device__ float g_vc [BB * SS * II];
__device__ float g_yt [BB * (ll)II * TT];
__device__ float g_f1 [BB * (ll)FFD * TT];
__device__ float g_f2 [BB * (ll)II * TT];
__device__ float g_sim[(ll)BB * HH * TT * TT];          // 402 MB
__device__ float g_col[(ll)BB * (FFD * KSZ) * TT];      // 453 MB im2col scratch
__device__ float g_gstats[BB * 32 * 2];

// ---------------- helpers -------------------------------------------------------
__device__ __forceinline__ float tf32r(float x) {
    unsigned r;
    asm("cvt.rna.tf32.f32 %0, %1;" : "=r"(r) : "f"(x));
    return __uint_as_float(r);
}

__device__ __forceinline__ void mma_tf32(float* c, const unsigned* a, const unsigned* b) {
    asm volatile(
        "mma.sync.aligned.m16n8k8.row.col.f32.tf32.tf32.f32 "
        "{%0,%1,%2,%3}, {%4,%5,%6,%7}, {%8,%9}, {%0,%1,%2,%3};"
        : "+f"(c[0]), "+f"(c[1]), "+f"(c[2]), "+f"(c[3])
        : "r"(a[0]), "r"(a[1]), "r"(a[2]), "r"(a[3]), "r"(b[0]), "r"(b[1]));
}

// ---------------- GroupNorm -----------------------------------------------------
__global__ void gn_stats_kernel(const float* __restrict__ x, float* __restrict__ stats) {
    __shared__ float rs[256], rq[256];
    int idx = blockIdx.x;
    const float* base = x + (ll)idx * 24 * TT;
    const int n = 24 * TT;
    float s = 0.f, q = 0.f;
    for (int i = threadIdx.x; i < n; i += 256) { float v = base[i]; s += v; q += v * v; }
    rs[threadIdx.x] = s; rq[threadIdx.x] = q; __syncthreads();
    for (int st = 128; st > 0; st >>= 1) {
        if (threadIdx.x < st) { rs[threadIdx.x] += rs[threadIdx.x + st]; rq[threadIdx.x] += rq[threadIdx.x + st]; }
        __syncthreads();
    }
    if (threadIdx.x == 0) {
        float mu = rs[0] / (float)n;
        float var = rq[0] / (float)n - mu * mu;
        stats[idx * 2 + 0] = mu;
        stats[idx * 2 + 1] = rsqrtf(var + 1e-6f);
    }
}

__global__ void gn_apply_kernel(const float* __restrict__ x, const float* __restrict__ stats,
                                const float* __restrict__ gs, const float* __restrict__ gb,
                                float* __restrict__ gt) {
    int bc = blockIdx.x;
    int b = bc / CC, c = bc % CC;
    int sidx = b * 32 + c / 24;
    float mu = stats[sidx * 2], rstd = stats[sidx * 2 + 1];
    float a = gs[c] * rstd;
    float bias = gb[c] - mu * a;
    const float* xr = x + (ll)bc * TT;
    float* gr = gt + (ll)b * TT * CC + c;
    for (int t = threadIdx.x; t < TT; t += 256)
        gr[(ll)t * CC] = xr[t] * a + bias;
}

// ---------------- unified TF32 tensor-core GEMM ---------------------------------
// C = alpha * A @ B(^T) (+ bias)(+res)(gelu)
// biasMode: 0=none, 1=per-n, 2=per-m
__global__ void __launch_bounds__(256)
gemm_mma_kernel(
    const float* __restrict__ A, ll sAb, ll sAh, int lda,
    const float* __restrict__ Bm, ll sBb, ll sBh, int ldb,
    float* __restrict__ Cm, ll sCb, ll sCh, int ldc,
    const float* __restrict__ bias,
    const float* __restrict__ res, ll sRb, ll sRh, int ldr,
    int M, int N, int K, float alpha, int zdiv, int transB, int biasMode, int act)
{
    __shared__ float As[KT][SLD];
    __shared__ float Bs[KT][SLD];
    int z = blockIdx.z, zb = z / zdiv, zh = z % zdiv;
    const float* Ab = A + zb * sAb + zh * sAh;
    const float* Bb = Bm + zb * sBb + zh * sBh;
    float* Cb = Cm + zb * sCb + zh * sCh;
    int m0 = blockIdx.y * 128, n0 = blockIdx.x * 128;
    int tid = threadIdx.x;
    int lane = tid & 31, wid = tid >> 5;
    int wm = wid >> 1, wn = wid & 1;          // 4 x 2 warp grid
    int g = lane >> 2, c = lane & 3;

    float acc[2][8][4];
#pragma unroll
    for (int i = 0; i < 2; i++)
#pragma unroll
        for (int j = 0; j < 8; j++)
#pragma unroll
            for (int e = 0; e < 4; e++) acc[i][j][e] = 0.f;

    int la_m = tid >> 1;            // 0..127
    int la_k = (tid & 1) * 16;      // 0 or 16
    int lb_k = tid >> 3;            // 0..31
    int lb_n = (tid & 7) * 16;      // 0..112

    for (int k0 = 0; k0 < K; k0 += KT) {
        // ---- A tile [128 m][KT k] -> As[k][m] (tf32-rounded) ----
        {
            int m = m0 + la_m;
            bool mok = (m < M);
            const float* ap = Ab + (ll)m * lda + k0 + la_k;
#pragma unroll
            for (int i = 0; i < 4; i++) {
                float4 vv = mok ? *(const float4*)(ap + i * 4) : make_float4(0.f, 0.f, 0.f, 0.f);
                As[la_k + i * 4 + 0][la_m] = tf32r(vv.x);
                As[la_k + i * 4 + 1][la_m] = tf32r(vv.y);
                As[la_k + i * 4 + 2][la_m] = tf32r(vv.z);
                As[la_k + i * 4 + 3][la_m] = tf32r(vv.w);
            }
        }
        // ---- B tile -> Bs[k][n] ----
        if (transB) {
            int n = n0 + la_m;
            bool nok = (n < N);
            const float* bp = Bb + (ll)n * ldb + k0 + la_k;
#pragma unroll
            for (int i = 0; i < 4; i++) {
                float4 vv = nok ? *(const float4*)(bp + i * 4) : make_float4(0.f, 0.f, 0.f, 0.f);
                Bs[la_k + i * 4 + 0][la_m] = tf32r(vv.x);
                Bs[la_k + i * 4 + 1][la_m] = tf32r(vv.y);
                Bs[la_k + i * 4 + 2][la_m] = tf32r(vv.z);
                Bs[la_k + i * 4 + 3][la_m] = tf32r(vv.w);
            }
        } else {
            int kk = k0 + lb_k;
            const float* bp = Bb + (ll)kk * ldb + n0 + lb_n;
#pragma unroll
            for (int i = 0; i < 4; i++) {
                int nbase = n0 + lb_n + i * 4;
                float4 vv;
                if (nbase + 3 < N) {
                    vv = *(const float4*)(bp + i * 4);
                } else {
                    vv.x = (nbase + 0 < N) ? bp[i * 4 + 0] : 0.f;
                    vv.y = (nbase + 1 < N) ? bp[i * 4 + 1] : 0.f;
                    vv.z = (nbase + 2 < N) ? bp[i * 4 + 2] : 0.f;
                    vv.w = (nbase + 3 < N) ? bp[i * 4 + 3] : 0.f;
                }
                Bs[lb_k][lb_n + i * 4 + 0] = tf32r(vv.x);
                Bs[lb_k][lb_n + i * 4 + 1] = tf32r(vv.y);
                Bs[lb_k][lb_n + i * 4 + 2] = tf32r(vv.z);
                Bs[lb_k][lb_n + i * 4 + 3] = tf32r(vv.w);
            }
        }
        __syncthreads();

#pragma unroll
        for (int ks = 0; ks < KT / 8; ks++) {
            int kb = ks * 8;
            unsigned af[2][4], bf[8][2];
#pragma unroll
            for (int mt = 0; mt < 2; mt++) {
                int mrow = wm * 32 + mt * 16;
                af[mt][0] = __float_as_uint(As[kb + c    ][mrow + g]);
                af[mt][1] = __float_as_uint(As[kb + c    ][mrow + g + 8]);
                af[mt][2] = __float_as_uint(As[kb + c + 4][mrow + g]);
                af[mt][3] = __float_as_uint(As[kb + c + 4][mrow + g + 8]);
            }
#pragma unroll
            for (int nt = 0; nt < 8; nt++) {
                int ncol = wn * 64 + nt * 8;
                bf[nt][0] = __float_as_uint(Bs[kb + c    ][ncol + g]);
                bf[nt][1] = __float_as_uint(Bs[kb + c + 4][ncol + g]);
            }
#pragma unroll
            for (int mt = 0; mt < 2; mt++)
#pragma unroll
                for (int nt = 0; nt < 8; nt++)
                    mma_tf32(acc[mt][nt], af[mt], bf[nt]);
        }
        __syncthreads();
    }

    // ---- epilogue ----
#pragma unroll
    for (int mt = 0; mt < 2; mt++) {
#pragma unroll
        for (int half = 0; half < 2; half++) {
            int m = m0 + wm * 32 + mt * 16 + g + half * 8;
            if (m >= M) continue;
            float bm = (biasMode == 2) ? bias[m] : 0.f;
            float* cr = Cb + (ll)m * ldc;
            const float* rr = res ? (res + zb * sRb + zh * sRh + (ll)m * ldr) : (const float*)0;
#pragma unroll
            for (int nt = 0; nt < 8; nt++) {
#pragma unroll
                for (int e = 0; e < 2; e++) {
                    int n = n0 + wn * 64 + nt * 8 + c * 2 + e;
                    if (n >= N) continue;
                    float v = acc[mt][nt][half * 2 + e] * alpha + bm;
                    if (biasMode == 1) v += bias[n];
                    if (rr) v += rr[n];
                    if (act) v = v * normcdff(v);
                    cr[n] = v;
                }
            }
        }
    }
}

// ---------------- im2col for conv1d (k=9, pad=4) --------------------------------
__global__ void im2col_kernel(const float* __restrict__ X, float* __restrict__ col, int Cin) {
    int j = blockIdx.x;                 // ch*9 + tap
    int b = blockIdx.y;
    int ch = j / KSZ, tap = j % KSZ;
    const float* xr = X + ((ll)b * Cin + ch) * TT;
    float* cr = col + ((ll)b * Cin * KSZ + j) * TT;
    int shift = tap - 4;
    for (int t = threadIdx.x; t < TT; t += 256) {
        int tp = t + shift;
        cr[t] = (tp >= 0 && tp < TT) ? xr[tp] : 0.f;
    }
}

// ---------------- LayerNorm -----------------------------------------------------
__global__ void ln_kernel(const float* __restrict__ x, const float* __restrict__ sc,
                          const float* __restrict__ bi, float* __restrict__ y, int transposed)
{
    __shared__ float red[256];
    int token = blockIdx.x;
    const float* xr = x + (ll)token * II;
    int tid = threadIdx.x;
    float v0 = xr[tid], v1 = xr[tid + 256], v2 = xr[tid + 512];
    red[tid] = v0 + v1 + v2; __syncthreads();
    for (int st = 128; st > 0; st >>= 1) {
        if (tid < st) red[tid] += red[tid + st];
        __syncthreads();
    }
    float mu = red[0] * (1.f / (float)II);
    __syncthreads();
    float d0 = v0 - mu, d1 = v1 - mu, d2 = v2 - mu;
    red[tid] = d0 * d0 + d1 * d1 + d2 * d2; __syncthreads();
    for (int st = 128; st > 0; st >>= 1) {
        if (tid < st) red[tid] += red[tid + st];
        __syncthreads();
    }
    float rstd = rsqrtf(red[0] * (1.f / (float)II) + 1e-5f);
    float o0 = d0 * rstd * sc[tid] + bi[tid];
    float o1 = d1 * rstd * sc[tid + 256] + bi[tid + 256];
    float o2 = d2 * rstd * sc[tid + 512] + bi[tid + 512];
    if (!transposed) {
        float* yr = y + (ll)token * II;
        yr[tid] = o0; yr[tid + 256] = o1; yr[tid + 512] = o2;
    } else {
        int b = token >> 11, t = token & (TT - 1);
        float* yb = y + (ll)b * II * TT + t;
        yb[(ll)tid * TT] = o0;
        yb[(ll)(tid + 256) * TT] = o1;
        yb[(ll)(tid + 512) * TT] = o2;
    }
}

// ---------------- row softmax ---------------------------------------------------
__global__ void softmax_kernel(float* __restrict__ sim) {
    __shared__ float buf[TT];
    __shared__ float red[256];
    ll row = blockIdx.x;
    float* p = sim + row * TT;
    int tid = threadIdx.x;
    float m = -1e30f;
    for (int i = tid; i < TT; i += 256) { float v = p[i]; buf[i] = v; m = fmaxf(m, v); }
    red[tid] = m; __syncthreads();
    for (int s = 128; s > 0; s >>= 1) {
        if (tid < s) red[tid] = fmaxf(red[tid], red[tid + s]);
        __syncthreads();
    }
    m = red[0]; __syncthreads();
    float sum = 0.f;
    for (int i = tid; i < TT; i += 256) { float e = expf(buf[i] - m); buf[i] = e; sum += e; }
    red[tid] = sum; __syncthreads();
    for (int s = 128; s > 0; s >>= 1) {
        if (tid < s) red[tid] += red[tid + s];
        __syncthreads();
    }
    float inv = 1.f / red[0];
    for (int i = tid; i < TT; i += 256) p[i] = buf[i] * inv;
}

// ---------------- cross-attention (16 keys) -------------------------------------
__global__ void cross_attn_kernel(const float* __restrict__ q, const float* __restrict__ kc,
                                  const float* __restrict__ vc, float* __restrict__ out)
{
    __shared__ float sq[HH][DH];
    int token = blockIdx.x;
    int b = token / TT;
    int wid = threadIdx.x >> 5, lane = threadIdx.x & 31;
    const float* qrow = q + (ll)token * II + wid * DH;
    sq[wid][lane] = qrow[lane];
    sq[wid][lane + 32] = qrow[lane + 32];
    __syncwarp();
    const float* kb = kc + (ll)b * SS * II + wid * DH;
    const float* vb = vc + (ll)b * SS * II + wid * DH;
    float s = -1e30f;
    if (lane < SS) {
        s = 0.f;
        const float* kr = kb + lane * II;
#pragma unroll
        for (int d = 0; d < DH; d++) s += sq[wid][d] * kr[d];
        s *= 0.125f;
    }
    float m = s;
    for (int o = 8; o >= 1; o >>= 1) m = fmaxf(m, __shfl_xor_sync(0xffffffffu, m, o));
    float e = (lane < SS) ? expf(s - m) : 0.f;
    float sum = e;
    for (int o = 8; o >= 1; o >>= 1) sum += __shfl_xor_sync(0xffffffffu, sum, o);
    float p = e / sum;
    float o0 = 0.f, o1 = 0.f;
#pragma unroll
    for (int j = 0; j < SS; j++) {
        float pj = __shfl_sync(0xffffffffu, p, j);
        const float* vr = vb + j * II;
        o0 += pj * vr[lane];
        o1 += pj * vr[lane + 32];
    }
    float* orow = out + (ll)token * II + wid * DH;
    orow[lane] = o0;
    orow[lane + 32] = o1;
}

// ---------------- misc elementwise ----------------------------------------------
__global__ void add_t_kernel(float* __restrict__ h, const float* __restrict__ f) {
    int token = blockIdx.x;
    int b = token >> 11, t = token & (TT - 1);
    float* hr = h + (ll)token * II;
    const float* fb = f + (ll)b * II * TT + t;
    int tid = threadIdx.x;
    hr[tid]       += fb[(ll)tid * TT];
    hr[tid + 256] += fb[(ll)(tid + 256) * TT];
    hr[tid + 512] += fb[(ll)(tid + 512) * TT];
}

__global__ void final_kernel(const float* __restrict__ proj, const float* __restrict__ x,
                             float* __restrict__ out) {
    int bc = blockIdx.x;
    int b = bc / CC, c = bc % CC;
    const float* pr = proj + (ll)b * TT * CC + c;
    const float* xr = x + (ll)bc * TT;
    float* orow = out + (ll)bc * TT;
    for (int t = threadIdx.x; t < TT; t += 256)
        orow[t] = pr[(ll)t * CC] + xr[t];
}

// ---------------- host orchestration --------------------------------------------
static void gemm(const float* A, ll sAb, ll sAh, int lda,
                 const float* Bm, ll sBb, ll sBh, int ldb, int transB,
                 float* Cm, ll sCb, ll sCh, int ldc,
                 const float* bias, int biasMode,
                 const float* res, ll sRb, ll sRh, int ldr,
                 int M, int N, int K, float alpha, int Z, int zdiv, int act)
{
    dim3 grid((N + 127) / 128, (M + 127) / 128, Z);
    gemm_mma_kernel<<<grid, 256>>>(A, sAb, sAh, lda, Bm, sBb, sBh, ldb,
                                   Cm, sCb, sCh, ldc, bias, res, sRb, sRh, ldr,
                                   M, N, K, alpha, zdiv, transB, biasMode, act);
}

extern "C" void kernel_launch(void* const* d_in, const int* in_sizes, int n_in,
                              void* d_out, int out_size)
{
    (void)in_sizes; (void)n_in; (void)out_size;
    const float* x      = (const float*)d_in[0];
    const float* ctx    = (const float*)d_in[1];
    const float* gn_s   = (const float*)d_in[2];
    const float* gn_b   = (const float*)d_in[3];
    const float* pin_w  = (const float*)d_in[4];
    const float* pin_b  = (const float*)d_in[5];
    const float* n1_s   = (const float*)d_in[6];
    const float* n1_b   = (const float*)d_in[7];
    const float* a1_wq  = (const float*)d_in[8];
    const float* a1_wk  = (const float*)d_in[9];
    const float* a1_wv  = (const float*)d_in[10];
    const float* a1_wo  = (const float*)d_in[11];
    const float* a1_bo  = (const float*)d_in[12];
    const float* n2_s   = (const float*)d_in[13];
    const float* n2_b   = (const float*)d_in[14];
    const float* a2_wq  = (const float*)d_in[15];
    const float* a2_wk  = (const float*)d_in[16];
    const float* a2_wv  = (const float*)d_in[17];
    const float* a2_wo  = (const float*)d_in[18];
    const float* a2_bo  = (const float*)d_in[19];
    const float* n3_s   = (const float*)d_in[20];
    const float* n3_b   = (const float*)d_in[21];
    const float* ff1_w  = (const float*)d_in[22];
    const float* ff1_b  = (const float*)d_in[23];
    const float* ff2_w  = (const float*)d_in[24];
    const float* ff2_b  = (const float*)d_in[25];
    const float* pout_w = (const float*)d_in[26];
    const float* pout_b = (const float*)d_in[27];

    float *gt, *h, *y, *q, *k, *v, *ao, *kc, *vc, *yt, *f1, *f2, *sim, *col, *stats;
    cudaGetSymbolAddress((void**)&gt, g_gt);
    cudaGetSymbolAddress((void**)&h, g_h);
    cudaGetSymbolAddress((void**)&y, g_y);
    cudaGetSymbolAddress((void**)&q, g_q);
    cudaGetSymbolAddress((void**)&k, g_k);
    cudaGetSymbolAddress((void**)&v, g_v);
    cudaGetSymbolAddress((void**)&ao, g_ao);
    cudaGetSymbolAddress((void**)&kc, g_kc);
    cudaGetSymbolAddress((void**)&vc, g_vc);
    cudaGetSymbolAddress((void**)&yt, g_yt);
    cudaGetSymbolAddress((void**)&f1, g_f1);
    cudaGetSymbolAddress((void**)&f2, g_f2);
    cudaGetSymbolAddress((void**)&sim, g_sim);
    cudaGetSymbolAddress((void**)&col, g_col);
    cudaGetSymbolAddress((void**)&stats, g_gstats);

    const ll TI = (ll)TT * II;
    const ll TC = (ll)TT * CC;
    const int J1 = II * KSZ;     // 6912
    const int J2 = FFD * KSZ;    // 27648

    // GroupNorm -> gt (token-major)
    gn_stats_kernel<<<BB * 32, 256>>>(x, stats);
    gn_apply_kernel<<<BB * CC, 256>>>(x, stats, gn_s, gn_b, gt);

    // proj_in
    gemm(gt, TC, 0, CC, pin_w, 0, 0, CC, 1, h, TI, 0, II,
         pin_b, 1, 0, 0, 0, 0, TT, II, CC, 1.f, BB, 1, 0);

    for (int d = 0; d < DEPTH; d++) {
        // ---- self attention ----
        ln_kernel<<<BB * TT, 256>>>(h, n1_s + d * II, n1_b + d * II, y, 0);
        gemm(y, TI, 0, II, a1_wq + (ll)d * II * II, 0, 0, II, 0, q, TI, 0, II,
             0, 0, 0, 0, 0, 0, TT, II, II, 1.f, BB, 1, 0);
        gemm(y, TI, 0, II, a1_wk + (ll)d * II * II, 0, 0, II, 0, k, TI, 0, II,
             0, 0, 0, 0, 0, 0, TT, II, II, 1.f, BB, 1, 0);
        gemm(y, TI, 0, II, a1_wv + (ll)d * II * II, 0, 0, II, 0, v, TI, 0, II,
             0, 0, 0, 0, 0, 0, TT, II, II, 1.f, BB, 1, 0);
        gemm(q, TI, DH, II, k, TI, DH, II, 1, sim, (ll)HH * TT * TT, (ll)TT * TT, TT,
             0, 0, 0, 0, 0, 0, TT, TT, DH, 0.125f, BB * HH, HH, 0);
        softmax_kernel<<<BB * HH * TT, 256>>>(sim);
        gemm(sim, (ll)HH * TT * TT, (ll)TT * TT, TT, v, TI, DH, II, 0, ao, TI, DH, II,
             0, 0, 0, 0, 0, 0, TT, DH, TT, 1.f, BB * HH, HH, 0);
        gemm(ao, TI, 0, II, a1_wo + (ll)d * II * II, 0, 0, II, 0, h, TI, 0, II,
             a1_bo + d * II, 1, h, TI, 0, II, TT, II, II, 1.f, BB, 1, 0);

        // ---- cross attention ----
        ln_kernel<<<BB * TT, 256>>>(h, n2_s + d * II, n2_b + d * II, y, 0);
        gemm(y, TI, 0, II, a2_wq + (ll)d * II * II, 0, 0, II, 0, q, TI, 0, II,
             0, 0, 0, 0, 0, 0, TT, II, II, 1.f, BB, 1, 0);
        gemm(ctx, (ll)SS * CTXD, 0, CTXD, a2_wk + (ll)d * CTXD * II, 0, 0, II, 0,
             kc, (ll)SS * II, 0, II, 0, 0, 0, 0, 0, 0, SS, II, CTXD, 1.f, BB, 1, 0);
        gemm(ctx, (ll)SS * CTXD, 0, CTXD, a2_wv + (ll)d * CTXD * II, 0, 0, II, 0,
             vc, (ll)SS * II, 0, II, 0, 0, 0, 0, 0, 0, SS, II, CTXD, 1.f, BB, 1, 0);
        cross_attn_kernel<<<BB * TT, HH * 32>>>(q, kc, vc, ao);
        gemm(ao, TI, 0, II, a2_wo + (ll)d * II * II, 0, 0, II, 0, h, TI, 0, II,
             a2_bo + d * II, 1, h, TI, 0, II, TT, II, II, 1.f, BB, 1, 0);

        // ---- conv feed-forward: im2col + GEMM ----
        ln_kernel<<<BB * TT, 256>>>(h, n3_s + d * II, n3_b + d * II, yt, 1);
        {
            dim3 gi1(J1, BB);
            im2col_kernel<<<gi1, 256>>>(yt, col, II);
            gemm(ff1_w + (ll)d * FFD * J1, 0, 0, J1,
                 col, (ll)J1 * TT, 0, TT, 0,
                 f1, (ll)FFD * TT, 0, TT,
                 ff1_b + d * FFD, 2, 0, 0, 0, 0,
                 FFD, TT, J1, 1.f, BB, 1, 1);
            dim3 gi2(J2, BB);
            im2col_kernel<<<gi2, 256>>>(f1, col, FFD);
            gemm(ff2_w + (ll)d * II * J2, 0, 0, J2,
                 col, (ll)J2 * TT, 0, TT, 0,
                 f2, (ll)II * TT, 0, TT,
                 ff2_b + d * II, 2, 0, 0, 0, 0,
                 II, TT, J2, 1.f, BB, 1, 0);
        }
        add_t_kernel<<<BB * TT, 256>>>(h, f2);
    }

    // proj_out + residual
    gemm(h, TI, 0, II, pout_w, 0, 0, II, 1, gt, TC, 0, CC,
         pout_b, 1, 0, 0, 0, 0, TT, CC, II, 1.f, BB, 1, 0);
    final_kernel<<<BB * CC, 256>>>(gt, x, (float*)d_out);
}